// round 14
// baseline (speedup 1.0000x reference)
#include <cuda_runtime.h>
#include <cuda_fp16.h>
#include <cstdint>

// ---------------------------------------------------------------------------
// SWMSA: B=32, H=W=56, E=256, NH=8, HD=32, WS=7, WD=49, NW=64, SS=3
// R14: fused attention+proj in ONE kernel. Blocks 0..4095 = attention
//      (R13 path), blocks 4096..7231 = proj (R13 path) gated on per-batch
//      completion counters (attention of batch b signals g_cnt[b]).
// ---------------------------------------------------------------------------

#define BATCH 32
#define HWPIX 3136
#define EDIM  256
#define WD    49
#define SCALE 0.17677669529663687f   // 1/sqrt(32)

__device__ __align__(16) __half g_mid[(size_t)BATCH * HWPIX * EDIM];
__device__ __align__(16) __half g_wpT[65536];    // proj_w^T fp16 [n][k]
__device__ __align__(16) __half g_qkvwT[3072];   // qkv_w^T fp16 [n][k]
__device__ __align__(16) __half g_bias[4 * 8 * 64 * 64];
__device__ int g_cnt[BATCH];

__device__ __forceinline__ void mma_f16(float* c, const uint32_t* a, const uint32_t* b) {
    asm volatile(
        "mma.sync.aligned.m16n8k16.row.col.f32.f16.f16.f32 "
        "{%0,%1,%2,%3}, {%4,%5,%6,%7}, {%8,%9}, {%0,%1,%2,%3};\n"
        : "+f"(c[0]), "+f"(c[1]), "+f"(c[2]), "+f"(c[3])
        : "r"(a[0]), "r"(a[1]), "r"(a[2]), "r"(a[3]), "r"(b[0]), "r"(b[1]));
}
__device__ __forceinline__ uint32_t h2u(__half2 h) { return *(uint32_t*)&h; }
__device__ __forceinline__ uint32_t packh2(float x, float y) {
    return h2u(__floats2half2_rn(x, y));
}
__device__ __forceinline__ void ldsm4(uint32_t& r0, uint32_t& r1, uint32_t& r2,
                                      uint32_t& r3, uint32_t addr) {
    asm volatile("ldmatrix.sync.aligned.m8n8.x4.shared.b16 {%0,%1,%2,%3}, [%4];"
                 : "=r"(r0), "=r"(r1), "=r"(r2), "=r"(r3) : "r"(addr));
}
__device__ __forceinline__ void ldsm4t(uint32_t& r0, uint32_t& r1, uint32_t& r2,
                                       uint32_t& r3, uint32_t addr) {
    asm volatile("ldmatrix.sync.aligned.m8n8.x4.trans.shared.b16 {%0,%1,%2,%3}, [%4];"
                 : "=r"(r0), "=r"(r1), "=r"(r2), "=r"(r3) : "r"(addr));
}
__device__ __forceinline__ void cpasync16(uint32_t s, const void* g) {
    asm volatile("cp.async.cg.shared.global [%0], [%1], 16;\n"
                 :: "r"(s), "l"(g) : "memory");
}

// ---------------- prep kernel ----------------
__global__ void __launch_bounds__(256)
swin_prep_kernel(const float* __restrict__ qkv_w,
                 const float* __restrict__ proj_w,
                 const float* __restrict__ rpb_table)
{
    int idx = blockIdx.x * 256 + threadIdx.x;   // grid 512 -> 131072
    if (idx < BATCH) g_cnt[idx] = 0;
    if (idx < 3072) {
        int n = idx >> 5, k = idx & 31;
        g_qkvwT[idx] = __float2half(qkv_w[k * 96 + n]);
    }
    if (idx < 65536) {
        int n = idx >> 8, k = idx & 255;
        g_wpT[idx] = __float2half(proj_w[k * 256 + n]);
    }
    {
        int cls = idx >> 15, h = (idx >> 12) & 7, i = (idx >> 6) & 63, j = idx & 63;
        float v = -30000.0f;
        if (i < WD && j < WD) {
            int tri = i / 7, tci = i - tri * 7;
            int trj = j / 7, tcj = j - trj * 7;
            int li = tri * 13 + tci, lj = trj * 13 + tcj;
            v = rpb_table[(li - lj + 84) * 8 + h];
            int bot = cls & 1, rgt = (cls >> 1) & 1;
            int ri = (bot ? (tri < 4 ? 1 : 2) : 0) * 3 + (rgt ? (tci < 4 ? 1 : 2) : 0);
            int rj = (bot ? (trj < 4 ? 1 : 2) : 0) * 3 + (rgt ? (tcj < 4 ? 1 : 2) : 0);
            if (ri != rj) v -= 100.0f;
        }
        g_bias[idx] = __float2half(v);
    }
}

// ---------------- fused kernel ----------------
// attention smem layout (words)
#define XROW    68
#define OFF_X   0
#define OFF_KV  4352
#define OFF_PIX 14592
#define OFF_QB  14656
#define OFF_W   14752
#define AT_SMEM_WORDS 16672
// proj smem layout (words)
#define PJ_BOFF 0
#define PJ_AOFF 8448
#define PJ_SMEM_WORDS (8448 + 2 * 2560)
// fused allocation = max of the two
#define FU_SMEM_WORDS AT_SMEM_WORDS
#define FU_SMEM_BYTES (FU_SMEM_WORDS * 4)

#define ATT_BLOCKS (BATCH * 128)         // 4096

__global__ void __launch_bounds__(256, 3)
swin_fused_kernel(const float* __restrict__ x,
                  const float* __restrict__ qkv_b,
                  const float* __restrict__ pb,
                  float* __restrict__ out)
{
    extern __shared__ uint32_t smw[];
    const int tid  = threadIdx.x;
    const int warp = tid >> 5;
    const int lane = tid & 31;
    const int bi   = blockIdx.x;

    if (bi < ATT_BLOCKS) {
        // ================= attention path (R13, unchanged) =================
        const int b    = bi >> 7;
        const int rem  = bi & 127;
        const int w    = rem >> 1;
        const int half = rem & 1;
        const int wr   = w >> 3, wc = w & 7;
        const int cls  = (wr == 7 ? 1 : 0) | (wc == 7 ? 2 : 0);

        const float* xb = x + (size_t)b * HWPIX * EDIM;
        __half*      ob = g_mid + (size_t)b * HWPIX * EDIM;

        float* qb   = (float*)(smw + OFF_QB);
        int*   pixs = (int*)(smw + OFF_PIX);
        const uint32_t sb = (uint32_t)__cvta_generic_to_shared(smw);

        for (int i = tid; i < 384; i += 256) {
            int row = i >> 2, c = i & 3;
            cpasync16(sb + ((OFF_W + row * 20 + (c << 2)) << 2),
                      (const char*)g_qkvwT + row * 64 + c * 16);
        }
        asm volatile("cp.async.commit_group;\n" ::: "memory");

        if (tid < 96) qb[tid] = qkv_b[tid];
        if (tid < 64) {
            int p = 0;
            if (tid < WD) {
                int tr = tid / 7, tc = tid - tr * 7;
                int sh = wr * 7 + tr + 3; if (sh >= 56) sh -= 56;
                int sw = wc * 7 + tc + 3; if (sw >= 56) sw -= 56;
                p = sh * 56 + sw;
            }
            pixs[tid] = p;
        }
        for (int i = tid; i < 15 * XROW; i += 256)
            smw[OFF_X + 49 * XROW + i] = 0u;

        for (int i = tid; i < 1568; i += 256) {
            int t  = i >> 5;
            int c4 = (i & 31) << 2;
            int tr = t / 7, tc = t - tr * 7;
            int sh = wr * 7 + tr + 3; if (sh >= 56) sh -= 56;
            int sw = wc * 7 + tc + 3; if (sw >= 56) sw -= 56;
            float4 v = *(const float4*)&xb[(sh * 56 + sw) * EDIM + (half << 7) + c4];
            smw[OFF_X + t * XROW + (c4 >> 1)]     = packh2(v.x, v.y);
            smw[OFF_X + t * XROW + (c4 >> 1) + 1] = packh2(v.z, v.w);
        }
        asm volatile("cp.async.wait_group 0;\n" ::: "memory");
        __syncthreads();

        const int hl = warp >> 1;
        const int h  = (half << 2) + hl;
        const int wm = warp & 1;
        const int tb = wm << 5;
        const int r  = lane >> 2;
        const int cc = lane & 3;

        const uint32_t sbK = sb + ((OFF_KV + hl * 2560) << 2);
        const uint32_t sbV = sbK + (1280 << 2);
        const uint32_t sbW = sb + (OFF_W << 2);
        uint32_t* Ksm = smw + OFF_KV + hl * 2560;
        uint32_t* Vsm = Ksm + 1280;

        uint32_t xa[2][2][4];
        #pragma unroll
        for (int mt = 0; mt < 2; mt++)
            #pragma unroll
            for (int kt = 0; kt < 2; kt++) {
                uint32_t addr = sb +
                    (((tb + (mt << 4) + (lane & 15)) * XROW +
                      (hl << 4) + (kt << 3) + ((lane >> 4) << 2)) << 2);
                ldsm4(xa[mt][kt][0], xa[mt][kt][1], xa[mt][kt][2], xa[mt][kt][3], addr);
            }

        uint32_t qf[2][2][4];
        #pragma unroll
        for (int sec = 0; sec < 3; sec++) {
            uint32_t bf[2][2][4];
            #pragma unroll
            for (int g = 0; g < 2; g++)
                #pragma unroll
                for (int kt = 0; kt < 2; kt++) {
                    uint32_t addr = sbW +
                        (((sec * 32 + (g << 4) + (lane & 15)) * 20 +
                          (kt << 3) + ((lane >> 4) << 2)) << 2);
                    ldsm4(bf[g][kt][0], bf[g][kt][1], bf[g][kt][2], bf[g][kt][3], addr);
                }
            #pragma unroll
            for (int mt = 0; mt < 2; mt++) {
                int tok0 = tb + (mt << 4) + r;
                #pragma unroll
                for (int nt = 0; nt < 4; nt++) {
                    int n0 = nt << 3;
                    float b0 = qb[sec * 32 + n0 + (cc << 1)];
                    float b1 = qb[sec * 32 + n0 + (cc << 1) + 1];
                    float c[4] = {b0, b1, b0, b1};
                    int g = nt >> 1, hi = nt & 1;
                    #pragma unroll
                    for (int kt = 0; kt < 2; kt++) {
                        uint32_t bb[2];
                        bb[0] = hi ? bf[g][kt][1] : bf[g][kt][0];
                        bb[1] = hi ? bf[g][kt][3] : bf[g][kt][2];
                        mma_f16(c, xa[mt][kt], bb);
                    }
                    if (sec == 0) {
                        int kt2 = nt >> 1;
                        if ((nt & 1) == 0) {
                            qf[mt][kt2][0] = packh2(c[0] * SCALE, c[1] * SCALE);
                            qf[mt][kt2][1] = packh2(c[2] * SCALE, c[3] * SCALE);
                        } else {
                            qf[mt][kt2][2] = packh2(c[0] * SCALE, c[1] * SCALE);
                            qf[mt][kt2][3] = packh2(c[2] * SCALE, c[3] * SCALE);
                        }
                    } else if (sec == 1) {
                        Ksm[tok0 * 20 + (nt << 2) + cc]       = packh2(c[0], c[1]);
                        Ksm[(tok0 + 8) * 20 + (nt << 2) + cc] = packh2(c[2], c[3]);
                    } else {
                        Vsm[tok0 * 20 + (nt << 2) + cc]       = packh2(c[0], c[1]);
                        Vsm[(tok0 + 8) * 20 + (nt << 2) + cc] = packh2(c[2], c[3]);
                    }
                }
            }
        }

        asm volatile("bar.sync %0, 64;" :: "r"(hl + 8) : "memory");

        const __half2* tb2 = (const __half2*)g_bias;

        #pragma unroll
        for (int mt = 0; mt < 2; mt++) {
            int q0 = tb + (mt << 4) + r;
            int base0 = ((((cls << 3) + h) << 6) + q0) << 5;
            int base1 = base0 + (8 << 5);

            float sacc[8][4];
            #pragma unroll
            for (int nt = 0; nt < 8; nt++)
                #pragma unroll
                for (int i = 0; i < 4; i++) sacc[nt][i] = 0.f;

            #pragma unroll
            for (int g = 0; g < 4; g++)
                #pragma unroll
                for (int kt = 0; kt < 2; kt++) {
                    uint32_t r0, r1, r2, r3;
                    uint32_t addr = sbK +
                        ((((g << 4) + (lane & 15)) * 20 + (kt << 3) + ((lane >> 4) << 2)) << 2);
                    ldsm4(r0, r1, r2, r3, addr);
                    uint32_t blo[2] = {r0, r2};
                    uint32_t bhi[2] = {r1, r3};
                    mma_f16(sacc[(g << 1)],     qf[mt][kt], blo);
                    mma_f16(sacc[(g << 1) + 1], qf[mt][kt], bhi);
                }

            #pragma unroll
            for (int nt = 0; nt < 8; nt++) {
                float2 b0 = __half22float2(tb2[base0 + (nt << 2) + cc]);
                float2 b1 = __half22float2(tb2[base1 + (nt << 2) + cc]);
                sacc[nt][0] += b0.x; sacc[nt][1] += b0.y;
                sacc[nt][2] += b1.x; sacc[nt][3] += b1.y;
            }
            float m0 = -1e30f, m1 = -1e30f;
            #pragma unroll
            for (int nt = 0; nt < 8; nt++) {
                m0 = fmaxf(m0, fmaxf(sacc[nt][0], sacc[nt][1]));
                m1 = fmaxf(m1, fmaxf(sacc[nt][2], sacc[nt][3]));
            }
            m0 = fmaxf(m0, __shfl_xor_sync(0xffffffffu, m0, 1));
            m0 = fmaxf(m0, __shfl_xor_sync(0xffffffffu, m0, 2));
            m1 = fmaxf(m1, __shfl_xor_sync(0xffffffffu, m1, 1));
            m1 = fmaxf(m1, __shfl_xor_sync(0xffffffffu, m1, 2));
            float s0 = 0.f, s1 = 0.f;
            #pragma unroll
            for (int nt = 0; nt < 8; nt++) {
                sacc[nt][0] = __expf(sacc[nt][0] - m0); s0 += sacc[nt][0];
                sacc[nt][1] = __expf(sacc[nt][1] - m0); s0 += sacc[nt][1];
                sacc[nt][2] = __expf(sacc[nt][2] - m1); s1 += sacc[nt][2];
                sacc[nt][3] = __expf(sacc[nt][3] - m1); s1 += sacc[nt][3];
            }
            s0 += __shfl_xor_sync(0xffffffffu, s0, 1);
            s0 += __shfl_xor_sync(0xffffffffu, s0, 2);
            s1 += __shfl_xor_sync(0xffffffffu, s1, 1);
            s1 += __shfl_xor_sync(0xffffffffu, s1, 2);
            float inv0 = __frcp_rn(s0), inv1 = __frcp_rn(s1);

            uint32_t pf[4][4];
            #pragma unroll
            for (int nt = 0; nt < 8; nt++) {
                int kt2 = nt >> 1;
                uint32_t plo = packh2(sacc[nt][0] * inv0, sacc[nt][1] * inv0);
                uint32_t phi = packh2(sacc[nt][2] * inv1, sacc[nt][3] * inv1);
                if ((nt & 1) == 0) { pf[kt2][0] = plo; pf[kt2][1] = phi; }
                else               { pf[kt2][2] = plo; pf[kt2][3] = phi; }
            }

            float oacc[4][4];
            #pragma unroll
            for (int nt = 0; nt < 4; nt++)
                #pragma unroll
                for (int i = 0; i < 4; i++) oacc[nt][i] = 0.f;

            #pragma unroll
            for (int kt2 = 0; kt2 < 4; kt2++)
                #pragma unroll
                for (int vh2 = 0; vh2 < 2; vh2++) {
                    uint32_t r0, r1, r2, r3;
                    uint32_t addr = sbV +
                        ((((kt2 << 4) + (lane & 15)) * 20 + (vh2 << 3) + ((lane >> 4) << 2)) << 2);
                    ldsm4t(r0, r1, r2, r3, addr);
                    uint32_t blo[2] = {r0, r1};
                    uint32_t bhi[2] = {r2, r3};
                    mma_f16(oacc[(vh2 << 1)],     pf[kt2], blo);
                    mma_f16(oacc[(vh2 << 1) + 1], pf[kt2], bhi);
                }

            #pragma unroll
            for (int ntv = 0; ntv < 4; ntv++) {
                int col = (h << 5) + (ntv << 3) + (cc << 1);
                if (q0 < WD)
                    *(uint32_t*)&ob[pixs[q0] * EDIM + col] = packh2(oacc[ntv][0], oacc[ntv][1]);
                if (q0 + 8 < WD)
                    *(uint32_t*)&ob[pixs[q0 + 8] * EDIM + col] = packh2(oacc[ntv][2], oacc[ntv][3]);
            }
        }

        // signal batch completion
        __syncthreads();
        if (tid == 0) {
            __threadfence();
            atomicAdd(&g_cnt[b], 1);
        }
    } else {
        // ================= proj path (R13, gated on counters) ==============
        const int pid = bi - ATT_BLOCKS;           // 0..3135
        const int rowBase = (pid >> 2) << 7;
        const int nBase   = (pid & 3) << 6;
        const int bf = rowBase / HWPIX;
        const int bl = (rowBase + 127) / HWPIX;

        if (tid == 0) {
            while (atomicAdd(&g_cnt[bf], 0) < 128) __nanosleep(128);
            if (bl != bf)
                while (atomicAdd(&g_cnt[bl], 0) < 128) __nanosleep(128);
        }
        __syncthreads();

        uint32_t* pjw = smw;
        const int mW = (warp >> 1) << 5;
        const int nW = (warp & 1) << 5;
        const __half* A16 = g_mid;
        const __half* B16 = g_wpT;
        const uint32_t sbase = (uint32_t)__cvta_generic_to_shared(pjw);

        float acc[2][4][4];
        #pragma unroll
        for (int mt = 0; mt < 2; mt++)
            #pragma unroll
            for (int nt = 0; nt < 4; nt++)
                #pragma unroll
                for (int i = 0; i < 4; i++)
                    acc[mt][nt][i] = 0.f;

        #pragma unroll
        for (int l = 0; l < 8; l++) {
            int idx = tid + (l << 8);
            int row = idx >> 5, c16 = idx & 31;
            cpasync16(sbase + ((PJ_BOFF + row * 132 + (c16 << 2)) << 2),
                      &B16[(size_t)(nBase + row) * 256 + (c16 << 3)]);
        }
        #pragma unroll
        for (int l = 0; l < 2; l++) {
            int idx = tid + (l << 8);
            int row = idx >> 2, c = idx & 3;
            cpasync16(sbase + ((PJ_AOFF + row * 20 + (c << 2)) << 2),
                      &A16[(size_t)(rowBase + row) * 256 + (c << 3)]);
        }
        asm volatile("cp.async.commit_group;\n" ::: "memory");
        #pragma unroll
        for (int l = 0; l < 2; l++) {
            int idx = tid + (l << 8);
            int row = idx >> 2, c = idx & 3;
            cpasync16(sbase + ((PJ_AOFF + 2560 + row * 20 + (c << 2)) << 2),
                      &A16[(size_t)(rowBase + row) * 256 + 32 + (c << 3)]);
        }
        asm volatile("cp.async.commit_group;\n" ::: "memory");

        for (int kc = 0; kc < 8; kc++) {
            int buf = kc & 1;
            if (kc < 7) asm volatile("cp.async.wait_group 1;\n" ::: "memory");
            else        asm volatile("cp.async.wait_group 0;\n" ::: "memory");
            __syncthreads();

            const uint32_t sbA = sbase + ((PJ_AOFF + buf * 2560) << 2);
            const uint32_t sbB = sbase + (PJ_BOFF << 2);
            #pragma unroll
            for (int kt = 0; kt < 2; kt++) {
                int bko = (kc << 4) + (kt << 3);
                uint32_t a[2][4];
                #pragma unroll
                for (int mt2 = 0; mt2 < 2; mt2++) {
                    uint32_t addr = sbA +
                        (((mW + (mt2 << 4) + (lane & 15)) * 20 +
                          (kt << 3) + ((lane >> 4) << 2)) << 2);
                    ldsm4(a[mt2][0], a[mt2][1], a[mt2][2], a[mt2][3], addr);
                }
                uint32_t bb[4][2];
                #pragma unroll
                for (int g = 0; g < 2; g++) {
                    uint32_t r0, r1, r2, r3;
                    uint32_t addr = sbB +
                        (((nW + (g << 4) + (lane & 15)) * 132 +
                          bko + ((lane >> 4) << 2)) << 2);
                    ldsm4(r0, r1, r2, r3, addr);
                    bb[(g << 1)][0]     = r0; bb[(g << 1)][1]     = r2;
                    bb[(g << 1) + 1][0] = r1; bb[(g << 1) + 1][1] = r3;
                }
                #pragma unroll
                for (int mt2 = 0; mt2 < 2; mt2++)
                    #pragma unroll
                    for (int nt = 0; nt < 4; nt++)
                        mma_f16(acc[mt2][nt], a[mt2], bb[nt]);
            }
            __syncthreads();

            if (kc < 6) {
                int k0 = (kc + 2) << 5;
                #pragma unroll
                for (int l = 0; l < 2; l++) {
                    int idx = tid + (l << 8);
                    int row = idx >> 2, c = idx & 3;
                    cpasync16(sbase + ((PJ_AOFF + buf * 2560 + row * 20 + (c << 2)) << 2),
                              &A16[(size_t)(rowBase + row) * 256 + k0 + (c << 3)]);
                }
                asm volatile("cp.async.commit_group;\n" ::: "memory");
            }
        }

        #pragma unroll
        for (int mt2 = 0; mt2 < 2; mt2++) {
            int row = rowBase + mW + (mt2 << 4) + (lane >> 2);
            #pragma unroll
            for (int nt = 0; nt < 4; nt++) {
                int col = nBase + nW + (nt << 3) + ((lane & 3) << 1);
                float b0 = pb[col], b1 = pb[col + 1];
                float2 v0 = make_float2(acc[mt2][nt][0] + b0, acc[mt2][nt][1] + b1);
                float2 v1 = make_float2(acc[mt2][nt][2] + b0, acc[mt2][nt][3] + b1);
                *(float2*)&out[(size_t)row * 256 + col]       = v0;
                *(float2*)&out[(size_t)(row + 8) * 256 + col] = v1;
            }
        }
    }
}

extern "C" void kernel_launch(void* const* d_in, const int* in_sizes, int n_in,
                              void* d_out, int out_size)
{
    (void)in_sizes; (void)n_in; (void)out_size;
    const float* x      = (const float*)d_in[0];
    const float* qkv_w  = (const float*)d_in[1];
    const float* qkv_b  = (const float*)d_in[2];
    const float* proj_w = (const float*)d_in[3];
    const float* proj_b = (const float*)d_in[4];
    const float* rpb    = (const float*)d_in[5];
    float* out = (float*)d_out;

    cudaFuncSetAttribute(swin_fused_kernel,
                         cudaFuncAttributeMaxDynamicSharedMemorySize, FU_SMEM_BYTES);

    swin_prep_kernel<<<512, 256>>>(qkv_w, proj_w, rpb);
    swin_fused_kernel<<<ATT_BLOCKS + 3136, 256, FU_SMEM_BYTES>>>(x, qkv_b, proj_b, out);
}

// round 16
// speedup vs baseline: 1.0550x; 1.0550x over previous
#include <cuda_runtime.h>
#include <cuda_fp16.h>
#include <cstdint>

// ---------------------------------------------------------------------------
// SWMSA: B=32, H=W=56, E=256, NH=8, HD=32, WS=7, WD=49, NW=64, SS=3
// R15: two kernels (fusion reverted). Attention smem 48.1KB via X/KV alias
//      (X dead after xa ldmatrix; extra barrier added), both kernels at
//      __launch_bounds__(256,4) -> 4 blocks/SM, 32 warps.
// ---------------------------------------------------------------------------

#define BATCH 32
#define HWPIX 3136
#define EDIM  256
#define WD    49
#define SCALE 0.17677669529663687f   // 1/sqrt(32)

__device__ __align__(16) __half g_mid[(size_t)BATCH * HWPIX * EDIM];
__device__ __align__(16) __half g_wpT[65536];    // proj_w^T fp16 [n][k]
__device__ __align__(16) __half g_qkvwT[3072];   // qkv_w^T fp16 [n][k]
__device__ __align__(16) __half g_bias[4 * 8 * 64 * 64];

__device__ __forceinline__ void mma_f16(float* c, const uint32_t* a, const uint32_t* b) {
    asm volatile(
        "mma.sync.aligned.m16n8k16.row.col.f32.f16.f16.f32 "
        "{%0,%1,%2,%3}, {%4,%5,%6,%7}, {%8,%9}, {%0,%1,%2,%3};\n"
        : "+f"(c[0]), "+f"(c[1]), "+f"(c[2]), "+f"(c[3])
        : "r"(a[0]), "r"(a[1]), "r"(a[2]), "r"(a[3]), "r"(b[0]), "r"(b[1]));
}
__device__ __forceinline__ uint32_t h2u(__half2 h) { return *(uint32_t*)&h; }
__device__ __forceinline__ uint32_t packh2(float x, float y) {
    return h2u(__floats2half2_rn(x, y));
}
__device__ __forceinline__ void ldsm4(uint32_t& r0, uint32_t& r1, uint32_t& r2,
                                      uint32_t& r3, uint32_t addr) {
    asm volatile("ldmatrix.sync.aligned.m8n8.x4.shared.b16 {%0,%1,%2,%3}, [%4];"
                 : "=r"(r0), "=r"(r1), "=r"(r2), "=r"(r3) : "r"(addr));
}
__device__ __forceinline__ void ldsm4t(uint32_t& r0, uint32_t& r1, uint32_t& r2,
                                       uint32_t& r3, uint32_t addr) {
    asm volatile("ldmatrix.sync.aligned.m8n8.x4.trans.shared.b16 {%0,%1,%2,%3}, [%4];"
                 : "=r"(r0), "=r"(r1), "=r"(r2), "=r"(r3) : "r"(addr));
}
__device__ __forceinline__ void cpasync16(uint32_t s, const void* g) {
    asm volatile("cp.async.cg.shared.global [%0], [%1], 16;\n"
                 :: "r"(s), "l"(g) : "memory");
}

// ---------------- prep kernel ----------------
__global__ void __launch_bounds__(256)
swin_prep_kernel(const float* __restrict__ qkv_w,
                 const float* __restrict__ proj_w,
                 const float* __restrict__ rpb_table)
{
    int idx = blockIdx.x * 256 + threadIdx.x;   // grid 512 -> 131072
    if (idx < 3072) {
        int n = idx >> 5, k = idx & 31;
        g_qkvwT[idx] = __float2half(qkv_w[k * 96 + n]);
    }
    if (idx < 65536) {
        int n = idx >> 8, k = idx & 255;
        g_wpT[idx] = __float2half(proj_w[k * 256 + n]);
    }
    {
        int cls = idx >> 15, h = (idx >> 12) & 7, i = (idx >> 6) & 63, j = idx & 63;
        float v = -30000.0f;
        if (i < WD && j < WD) {
            int tri = i / 7, tci = i - tri * 7;
            int trj = j / 7, tcj = j - trj * 7;
            int li = tri * 13 + tci, lj = trj * 13 + tcj;
            v = rpb_table[(li - lj + 84) * 8 + h];
            int bot = cls & 1, rgt = (cls >> 1) & 1;
            int ri = (bot ? (tri < 4 ? 1 : 2) : 0) * 3 + (rgt ? (tci < 4 ? 1 : 2) : 0);
            int rj = (bot ? (trj < 4 ? 1 : 2) : 0) * 3 + (rgt ? (tcj < 4 ? 1 : 2) : 0);
            if (ri != rj) v -= 100.0f;
        }
        g_bias[idx] = __float2half(v);
    }
}

// ---------------- attention kernel (X aliased over KV region) ----------------
#define XROW    68                 // X: 64 rows x 68 words, lives inside KV region
#define OFF_X   0
#define OFF_KV  0                  // 4 heads x 2560 words (K 64x20, V 64x20)
#define OFF_PIX 10240              // 64 ints
#define OFF_QB  10304              // 96 floats
#define OFF_W   10400              // 96 rows x 20 words
#define AT_SMEM_WORDS 12320        // 48.1 KB
#define AT_SMEM_BYTES (AT_SMEM_WORDS * 4)

__global__ void __launch_bounds__(256, 4)
swin_attn_kernel(const float* __restrict__ x,
                 const float* __restrict__ qkv_b)
{
    extern __shared__ uint32_t smw[];
    const int tid  = threadIdx.x;
    const int warp = tid >> 5;
    const int lane = tid & 31;
    const int bi   = blockIdx.x;
    const int b    = bi >> 7;
    const int rem  = bi & 127;
    const int w    = rem >> 1;
    const int half = rem & 1;
    const int wr   = w >> 3, wc = w & 7;
    const int cls  = (wr == 7 ? 1 : 0) | (wc == 7 ? 2 : 0);

    const float* xb = x + (size_t)b * HWPIX * EDIM;
    __half*      ob = g_mid + (size_t)b * HWPIX * EDIM;

    float* qb   = (float*)(smw + OFF_QB);
    int*   pixs = (int*)(smw + OFF_PIX);
    const uint32_t sb = (uint32_t)__cvta_generic_to_shared(smw);

    // ---- stage qkv weights (separate region, safe from X/KV alias) ----
    for (int i = tid; i < 384; i += 256) {
        int row = i >> 2, c = i & 3;
        cpasync16(sb + ((OFF_W + row * 20 + (c << 2)) << 2),
                  (const char*)g_qkvwT + row * 64 + c * 16);
    }
    asm volatile("cp.async.commit_group;\n" ::: "memory");

    // ---- init: qkv bias, pix LUT, X pad rows ----
    if (tid < 96) qb[tid] = qkv_b[tid];
    if (tid < 64) {
        int p = 0;
        if (tid < WD) {
            int tr = tid / 7, tc = tid - tr * 7;
            int sh = wr * 7 + tr + 3; if (sh >= 56) sh -= 56;
            int sw = wc * 7 + tc + 3; if (sw >= 56) sw -= 56;
            p = sh * 56 + sw;
        }
        pixs[tid] = p;
    }
    for (int i = tid; i < 15 * XROW; i += 256)
        smw[OFF_X + 49 * XROW + i] = 0u;        // zero X pad rows 49..63

    // ---- X load: 49 rows x 128 floats (this block's half) ----
    for (int i = tid; i < 1568; i += 256) {
        int t  = i >> 5;
        int c4 = (i & 31) << 2;
        int tr = t / 7, tc = t - tr * 7;
        int sh = wr * 7 + tr + 3; if (sh >= 56) sh -= 56;
        int sw = wc * 7 + tc + 3; if (sw >= 56) sw -= 56;
        float4 v = *(const float4*)&xb[(sh * 56 + sw) * EDIM + (half << 7) + c4];
        smw[OFF_X + t * XROW + (c4 >> 1)]     = packh2(v.x, v.y);
        smw[OFF_X + t * XROW + (c4 >> 1) + 1] = packh2(v.z, v.w);
    }
    asm volatile("cp.async.wait_group 0;\n" ::: "memory");
    __syncthreads();

    // ---- per-warp role ----
    const int hl = warp >> 1;
    const int h  = (half << 2) + hl;
    const int wm = warp & 1;
    const int tb = wm << 5;
    const int r  = lane >> 2;
    const int cc = lane & 3;

    const uint32_t sbK = sb + ((OFF_KV + hl * 2560) << 2);
    const uint32_t sbV = sbK + (1280 << 2);
    const uint32_t sbW = sb + (OFF_W << 2);
    uint32_t* Ksm = smw + OFF_KV + hl * 2560;
    uint32_t* Vsm = Ksm + 1280;

    // ---- X A-frags (X consumed into regs here) ----
    uint32_t xa[2][2][4];
    #pragma unroll
    for (int mt = 0; mt < 2; mt++)
        #pragma unroll
        for (int kt = 0; kt < 2; kt++) {
            uint32_t addr = sb +
                (((tb + (mt << 4) + (lane & 15)) * XROW +
                  (hl << 4) + (kt << 3) + ((lane >> 4) << 2)) << 2);
            ldsm4(xa[mt][kt][0], xa[mt][kt][1], xa[mt][kt][2], xa[mt][kt][3], addr);
        }
    __syncthreads();   // X fully consumed; K/V may now overwrite the X region

    // ---- QKV via smem weights ----
    uint32_t qf[2][2][4];
    #pragma unroll
    for (int sec = 0; sec < 3; sec++) {
        uint32_t bf[2][2][4];
        #pragma unroll
        for (int g = 0; g < 2; g++)
            #pragma unroll
            for (int kt = 0; kt < 2; kt++) {
                uint32_t addr = sbW +
                    (((sec * 32 + (g << 4) + (lane & 15)) * 20 +
                      (kt << 3) + ((lane >> 4) << 2)) << 2);
                ldsm4(bf[g][kt][0], bf[g][kt][1], bf[g][kt][2], bf[g][kt][3], addr);
            }
        #pragma unroll
        for (int mt = 0; mt < 2; mt++) {
            int tok0 = tb + (mt << 4) + r;
            #pragma unroll
            for (int nt = 0; nt < 4; nt++) {
                int n0 = nt << 3;
                float b0 = qb[sec * 32 + n0 + (cc << 1)];
                float b1 = qb[sec * 32 + n0 + (cc << 1) + 1];
                float c[4] = {b0, b1, b0, b1};
                int g = nt >> 1, hi = nt & 1;
                #pragma unroll
                for (int kt = 0; kt < 2; kt++) {
                    uint32_t bb[2];
                    bb[0] = hi ? bf[g][kt][1] : bf[g][kt][0];
                    bb[1] = hi ? bf[g][kt][3] : bf[g][kt][2];
                    mma_f16(c, xa[mt][kt], bb);
                }
                if (sec == 0) {
                    int kt2 = nt >> 1;
                    if ((nt & 1) == 0) {
                        qf[mt][kt2][0] = packh2(c[0] * SCALE, c[1] * SCALE);
                        qf[mt][kt2][1] = packh2(c[2] * SCALE, c[3] * SCALE);
                    } else {
                        qf[mt][kt2][2] = packh2(c[0] * SCALE, c[1] * SCALE);
                        qf[mt][kt2][3] = packh2(c[2] * SCALE, c[3] * SCALE);
                    }
                } else if (sec == 1) {
                    Ksm[tok0 * 20 + (nt << 2) + cc]       = packh2(c[0], c[1]);
                    Ksm[(tok0 + 8) * 20 + (nt << 2) + cc] = packh2(c[2], c[3]);
                } else {
                    Vsm[tok0 * 20 + (nt << 2) + cc]       = packh2(c[0], c[1]);
                    Vsm[(tok0 + 8) * 20 + (nt << 2) + cc] = packh2(c[2], c[3]);
                }
            }
        }
    }

    asm volatile("bar.sync %0, 64;" :: "r"(hl + 8) : "memory");

    const __half2* tb2 = (const __half2*)g_bias;

    #pragma unroll
    for (int mt = 0; mt < 2; mt++) {
        int q0 = tb + (mt << 4) + r;
        int base0 = ((((cls << 3) + h) << 6) + q0) << 5;
        int base1 = base0 + (8 << 5);

        float sacc[8][4];
        #pragma unroll
        for (int nt = 0; nt < 8; nt++)
            #pragma unroll
            for (int i = 0; i < 4; i++) sacc[nt][i] = 0.f;

        #pragma unroll
        for (int g = 0; g < 4; g++)
            #pragma unroll
            for (int kt = 0; kt < 2; kt++) {
                uint32_t r0, r1, r2, r3;
                uint32_t addr = sbK +
                    ((((g << 4) + (lane & 15)) * 20 + (kt << 3) + ((lane >> 4) << 2)) << 2);
                ldsm4(r0, r1, r2, r3, addr);
                uint32_t blo[2] = {r0, r2};
                uint32_t bhi[2] = {r1, r3};
                mma_f16(sacc[(g << 1)],     qf[mt][kt], blo);
                mma_f16(sacc[(g << 1) + 1], qf[mt][kt], bhi);
            }

        #pragma unroll
        for (int nt = 0; nt < 8; nt++) {
            float2 b0 = __half22float2(tb2[base0 + (nt << 2) + cc]);
            float2 b1 = __half22float2(tb2[base1 + (nt << 2) + cc]);
            sacc[nt][0] += b0.x; sacc[nt][1] += b0.y;
            sacc[nt][2] += b1.x; sacc[nt][3] += b1.y;
        }
        float m0 = -1e30f, m1 = -1e30f;
        #pragma unroll
        for (int nt = 0; nt < 8; nt++) {
            m0 = fmaxf(m0, fmaxf(sacc[nt][0], sacc[nt][1]));
            m1 = fmaxf(m1, fmaxf(sacc[nt][2], sacc[nt][3]));
        }
        m0 = fmaxf(m0, __shfl_xor_sync(0xffffffffu, m0, 1));
        m0 = fmaxf(m0, __shfl_xor_sync(0xffffffffu, m0, 2));
        m1 = fmaxf(m1, __shfl_xor_sync(0xffffffffu, m1, 1));
        m1 = fmaxf(m1, __shfl_xor_sync(0xffffffffu, m1, 2));
        float s0 = 0.f, s1 = 0.f;
        #pragma unroll
        for (int nt = 0; nt < 8; nt++) {
            sacc[nt][0] = __expf(sacc[nt][0] - m0); s0 += sacc[nt][0];
            sacc[nt][1] = __expf(sacc[nt][1] - m0); s0 += sacc[nt][1];
            sacc[nt][2] = __expf(sacc[nt][2] - m1); s1 += sacc[nt][2];
            sacc[nt][3] = __expf(sacc[nt][3] - m1); s1 += sacc[nt][3];
        }
        s0 += __shfl_xor_sync(0xffffffffu, s0, 1);
        s0 += __shfl_xor_sync(0xffffffffu, s0, 2);
        s1 += __shfl_xor_sync(0xffffffffu, s1, 1);
        s1 += __shfl_xor_sync(0xffffffffu, s1, 2);
        float inv0 = __frcp_rn(s0), inv1 = __frcp_rn(s1);

        uint32_t pf[4][4];
        #pragma unroll
        for (int nt = 0; nt < 8; nt++) {
            int kt2 = nt >> 1;
            uint32_t plo = packh2(sacc[nt][0] * inv0, sacc[nt][1] * inv0);
            uint32_t phi = packh2(sacc[nt][2] * inv1, sacc[nt][3] * inv1);
            if ((nt & 1) == 0) { pf[kt2][0] = plo; pf[kt2][1] = phi; }
            else               { pf[kt2][2] = plo; pf[kt2][3] = phi; }
        }

        float oacc[4][4];
        #pragma unroll
        for (int nt = 0; nt < 4; nt++)
            #pragma unroll
            for (int i = 0; i < 4; i++) oacc[nt][i] = 0.f;

        #pragma unroll
        for (int kt2 = 0; kt2 < 4; kt2++)
            #pragma unroll
            for (int vh2 = 0; vh2 < 2; vh2++) {
                uint32_t r0, r1, r2, r3;
                uint32_t addr = sbV +
                    ((((kt2 << 4) + (lane & 15)) * 20 + (vh2 << 3) + ((lane >> 4) << 2)) << 2);
                ldsm4t(r0, r1, r2, r3, addr);
                uint32_t blo[2] = {r0, r1};
                uint32_t bhi[2] = {r2, r3};
                mma_f16(oacc[(vh2 << 1)],     pf[kt2], blo);
                mma_f16(oacc[(vh2 << 1) + 1], pf[kt2], bhi);
            }

        #pragma unroll
        for (int ntv = 0; ntv < 4; ntv++) {
            int col = (h << 5) + (ntv << 3) + (cc << 1);
            if (q0 < WD)
                *(uint32_t*)&ob[pixs[q0] * EDIM + col] = packh2(oacc[ntv][0], oacc[ntv][1]);
            if (q0 + 8 < WD)
                *(uint32_t*)&ob[pixs[q0 + 8] * EDIM + col] = packh2(oacc[ntv][2], oacc[ntv][3]);
        }
    }
}

// ---------------------------------------------------------------------------
// Projection (R13 body, 4 blocks/SM): out = g_mid @ g_wpT^T + proj_b
// ---------------------------------------------------------------------------
#define PJ_BOFF 0
#define PJ_AOFF 8448
#define PJ_SMEM_WORDS (8448 + 2 * 2560)
#define PJ_SMEM_BYTES (PJ_SMEM_WORDS * 4)

__global__ void __launch_bounds__(256, 4)
swin_proj_kernel(const float* __restrict__ pb,
                 float* __restrict__ out)
{
    extern __shared__ uint32_t pjw[];
    const int tid  = threadIdx.x;
    const int lane = tid & 31;
    const int warp = tid >> 5;
    const int mW = (warp >> 1) << 5;
    const int nW = (warp & 1) << 5;
    const int rowBase = blockIdx.y << 7;
    const int nBase   = blockIdx.x << 6;
    const __half* A16 = g_mid;
    const __half* B16 = g_wpT;
    const uint32_t sbase = (uint32_t)__cvta_generic_to_shared(pjw);

    float acc[2][4][4];
    #pragma unroll
    for (int mt = 0; mt < 2; mt++)
        #pragma unroll
        for (int nt = 0; nt < 4; nt++)
            #pragma unroll
            for (int i = 0; i < 4; i++)
                acc[mt][nt][i] = 0.f;

    #pragma unroll
    for (int l = 0; l < 8; l++) {
        int idx = tid + (l << 8);
        int row = idx >> 5, c16 = idx & 31;
        cpasync16(sbase + ((PJ_BOFF + row * 132 + (c16 << 2)) << 2),
                  &B16[(size_t)(nBase + row) * 256 + (c16 << 3)]);
    }
    #pragma unroll
    for (int l = 0; l < 2; l++) {
        int idx = tid + (l << 8);
        int row = idx >> 2, c = idx & 3;
        cpasync16(sbase + ((PJ_AOFF + row * 20 + (c << 2)) << 2),
                  &A16[(size_t)(rowBase + row) * 256 + (c << 3)]);
    }
    asm volatile("cp.async.commit_group;\n" ::: "memory");
    #pragma unroll
    for (int l = 0; l < 2; l++) {
        int idx = tid + (l << 8);
        int row = idx >> 2, c = idx & 3;
        cpasync16(sbase + ((PJ_AOFF + 2560 + row * 20 + (c << 2)) << 2),
                  &A16[(size_t)(rowBase + row) * 256 + 32 + (c << 3)]);
    }
    asm volatile("cp.async.commit_group;\n" ::: "memory");

    for (int kc = 0; kc < 8; kc++) {
        int buf = kc & 1;
        if (kc < 7) asm volatile("cp.async.wait_group 1;\n" ::: "memory");
        else        asm volatile("cp.async.wait_group 0;\n" ::: "memory");
        __syncthreads();

        const uint32_t sbA = sbase + ((PJ_AOFF + buf * 2560) << 2);
        const uint32_t sbB = sbase + (PJ_BOFF << 2);
        #pragma unroll
        for (int kt = 0; kt < 2; kt++) {
            int bko = (kc << 4) + (kt << 3);
            uint32_t a[2][4];
            #pragma unroll
            for (int mt2 = 0; mt2 < 2; mt2++) {
                uint32_t addr = sbA +
                    (((mW + (mt2 << 4) + (lane & 15)) * 20 +
                      (kt << 3) + ((lane >> 4) << 2)) << 2);
                ldsm4(a[mt2][0], a[mt2][1], a[mt2][2], a[mt2][3], addr);
            }
            uint32_t bb[4][2];
            #pragma unroll
            for (int g = 0; g < 2; g++) {
                uint32_t r0, r1, r2, r3;
                uint32_t addr = sbB +
                    (((nW + (g << 4) + (lane & 15)) * 132 +
                      bko + ((lane >> 4) << 2)) << 2);
                ldsm4(r0, r1, r2, r3, addr);
                bb[(g << 1)][0]     = r0; bb[(g << 1)][1]     = r2;
                bb[(g << 1) + 1][0] = r1; bb[(g << 1) + 1][1] = r3;
            }
            #pragma unroll
            for (int mt2 = 0; mt2 < 2; mt2++)
                #pragma unroll
                for (int nt = 0; nt < 4; nt++)
                    mma_f16(acc[mt2][nt], a[mt2], bb[nt]);
        }
        __syncthreads();

        if (kc < 6) {
            int k0 = (kc + 2) << 5;
            #pragma unroll
            for (int l = 0; l < 2; l++) {
                int idx = tid + (l << 8);
                int row = idx >> 2, c = idx & 3;
                cpasync16(sbase + ((PJ_AOFF + buf * 2560 + row * 20 + (c << 2)) << 2),
                          &A16[(size_t)(rowBase + row) * 256 + k0 + (c << 3)]);
            }
            asm volatile("cp.async.commit_group;\n" ::: "memory");
        }
    }

    #pragma unroll
    for (int mt2 = 0; mt2 < 2; mt2++) {
        int row = rowBase + mW + (mt2 << 4) + (lane >> 2);
        #pragma unroll
        for (int nt = 0; nt < 4; nt++) {
            int col = nBase + nW + (nt << 3) + ((lane & 3) << 1);
            float b0 = pb[col], b1 = pb[col + 1];
            float2 v0 = make_float2(acc[mt2][nt][0] + b0, acc[mt2][nt][1] + b1);
            float2 v1 = make_float2(acc[mt2][nt][2] + b0, acc[mt2][nt][3] + b1);
            *(float2*)&out[(size_t)row * 256 + col]       = v0;
            *(float2*)&out[(size_t)(row + 8) * 256 + col] = v1;
        }
    }
}

extern "C" void kernel_launch(void* const* d_in, const int* in_sizes, int n_in,
                              void* d_out, int out_size)
{
    (void)in_sizes; (void)n_in; (void)out_size;
    const float* x      = (const float*)d_in[0];
    const float* qkv_w  = (const float*)d_in[1];
    const float* qkv_b  = (const float*)d_in[2];
    const float* proj_w = (const float*)d_in[3];
    const float* proj_b = (const float*)d_in[4];
    const float* rpb    = (const float*)d_in[5];
    float* out = (float*)d_out;

    cudaFuncSetAttribute(swin_attn_kernel,
                         cudaFuncAttributeMaxDynamicSharedMemorySize, AT_SMEM_BYTES);
    cudaFuncSetAttribute(swin_proj_kernel,
                         cudaFuncAttributeMaxDynamicSharedMemorySize, PJ_SMEM_BYTES);

    swin_prep_kernel<<<512, 256>>>(qkv_w, proj_w, rpb);
    swin_attn_kernel<<<BATCH * 128, 256, AT_SMEM_BYTES>>>(x, qkv_b);
    swin_proj_kernel<<<dim3(4, 784), 256, PJ_SMEM_BYTES>>>(proj_b, out);
}

// round 17
// speedup vs baseline: 1.0840x; 1.0275x over previous
#include <cuda_runtime.h>
#include <cuda_fp16.h>
#include <cstdint>

// ---------------------------------------------------------------------------
// SWMSA: B=32, H=W=56, E=256, NH=8, HD=32, WS=7, WD=49, NW=64, SS=3
// R17: R16 bodies fused into ONE kernel at 4 blocks/SM (54.3KB smem, 64-reg
//      cap). Blocks 0..4095 attention (X/KV-aliased path) -> signal g_cnt[b];
//      blocks 4096..7231 proj, gated per-batch on g_cnt.
// ---------------------------------------------------------------------------

#define BATCH 32
#define HWPIX 3136
#define EDIM  256
#define WD    49
#define SCALE 0.17677669529663687f   // 1/sqrt(32)

__device__ __align__(16) __half g_mid[(size_t)BATCH * HWPIX * EDIM];
__device__ __align__(16) __half g_wpT[65536];    // proj_w^T fp16 [n][k]
__device__ __align__(16) __half g_qkvwT[3072];   // qkv_w^T fp16 [n][k]
__device__ __align__(16) __half g_bias[4 * 8 * 64 * 64];
__device__ int g_cnt[BATCH];

__device__ __forceinline__ void mma_f16(float* c, const uint32_t* a, const uint32_t* b) {
    asm volatile(
        "mma.sync.aligned.m16n8k16.row.col.f32.f16.f16.f32 "
        "{%0,%1,%2,%3}, {%4,%5,%6,%7}, {%8,%9}, {%0,%1,%2,%3};\n"
        : "+f"(c[0]), "+f"(c[1]), "+f"(c[2]), "+f"(c[3])
        : "r"(a[0]), "r"(a[1]), "r"(a[2]), "r"(a[3]), "r"(b[0]), "r"(b[1]));
}
__device__ __forceinline__ uint32_t h2u(__half2 h) { return *(uint32_t*)&h; }
__device__ __forceinline__ uint32_t packh2(float x, float y) {
    return h2u(__floats2half2_rn(x, y));
}
__device__ __forceinline__ void ldsm4(uint32_t& r0, uint32_t& r1, uint32_t& r2,
                                      uint32_t& r3, uint32_t addr) {
    asm volatile("ldmatrix.sync.aligned.m8n8.x4.shared.b16 {%0,%1,%2,%3}, [%4];"
                 : "=r"(r0), "=r"(r1), "=r"(r2), "=r"(r3) : "r"(addr));
}
__device__ __forceinline__ void ldsm4t(uint32_t& r0, uint32_t& r1, uint32_t& r2,
                                       uint32_t& r3, uint32_t addr) {
    asm volatile("ldmatrix.sync.aligned.m8n8.x4.trans.shared.b16 {%0,%1,%2,%3}, [%4];"
                 : "=r"(r0), "=r"(r1), "=r"(r2), "=r"(r3) : "r"(addr));
}
__device__ __forceinline__ void cpasync16(uint32_t s, const void* g) {
    asm volatile("cp.async.cg.shared.global [%0], [%1], 16;\n"
                 :: "r"(s), "l"(g) : "memory");
}

// ---------------- prep kernel ----------------
__global__ void __launch_bounds__(256)
swin_prep_kernel(const float* __restrict__ qkv_w,
                 const float* __restrict__ proj_w,
                 const float* __restrict__ rpb_table)
{
    int idx = blockIdx.x * 256 + threadIdx.x;   // grid 512 -> 131072
    if (idx < BATCH) g_cnt[idx] = 0;
    if (idx < 3072) {
        int n = idx >> 5, k = idx & 31;
        g_qkvwT[idx] = __float2half(qkv_w[k * 96 + n]);
    }
    if (idx < 65536) {
        int n = idx >> 8, k = idx & 255;
        g_wpT[idx] = __float2half(proj_w[k * 256 + n]);
    }
    {
        int cls = idx >> 15, h = (idx >> 12) & 7, i = (idx >> 6) & 63, j = idx & 63;
        float v = -30000.0f;
        if (i < WD && j < WD) {
            int tri = i / 7, tci = i - tri * 7;
            int trj = j / 7, tcj = j - trj * 7;
            int li = tri * 13 + tci, lj = trj * 13 + tcj;
            v = rpb_table[(li - lj + 84) * 8 + h];
            int bot = cls & 1, rgt = (cls >> 1) & 1;
            int ri = (bot ? (tri < 4 ? 1 : 2) : 0) * 3 + (rgt ? (tci < 4 ? 1 : 2) : 0);
            int rj = (bot ? (trj < 4 ? 1 : 2) : 0) * 3 + (rgt ? (tcj < 4 ? 1 : 2) : 0);
            if (ri != rj) v -= 100.0f;
        }
        g_bias[idx] = __float2half(v);
    }
}

// ---------------- fused kernel ----------------
// attention smem layout (words) — X aliased over KV region (R16 proven)
#define XROW    68
#define OFF_X   0
#define OFF_KV  0
#define OFF_PIX 10240
#define OFF_QB  10304
#define OFF_W   10400
#define AT_SMEM_WORDS 12320
// proj smem layout (words)
#define PJ_BOFF 0
#define PJ_AOFF 8448
#define PJ_SMEM_WORDS (8448 + 2 * 2560)   // 13568
// fused allocation = max
#define FU_SMEM_WORDS PJ_SMEM_WORDS
#define FU_SMEM_BYTES (FU_SMEM_WORDS * 4)

#define ATT_BLOCKS (BATCH * 128)          // 4096

__global__ void __launch_bounds__(256, 4)
swin_fused_kernel(const float* __restrict__ x,
                  const float* __restrict__ qkv_b,
                  const float* __restrict__ pb,
                  float* __restrict__ out)
{
    extern __shared__ uint32_t smw[];
    const int tid  = threadIdx.x;
    const int warp = tid >> 5;
    const int lane = tid & 31;
    const int bi   = blockIdx.x;

    if (bi < ATT_BLOCKS) {
        // ================= attention path (R16, byte-identical) ============
        const int b    = bi >> 7;
        const int rem  = bi & 127;
        const int w    = rem >> 1;
        const int half = rem & 1;
        const int wr   = w >> 3, wc = w & 7;
        const int cls  = (wr == 7 ? 1 : 0) | (wc == 7 ? 2 : 0);

        const float* xb = x + (size_t)b * HWPIX * EDIM;
        __half*      ob = g_mid + (size_t)b * HWPIX * EDIM;

        float* qb   = (float*)(smw + OFF_QB);
        int*   pixs = (int*)(smw + OFF_PIX);
        const uint32_t sb = (uint32_t)__cvta_generic_to_shared(smw);

        for (int i = tid; i < 384; i += 256) {
            int row = i >> 2, c = i & 3;
            cpasync16(sb + ((OFF_W + row * 20 + (c << 2)) << 2),
                      (const char*)g_qkvwT + row * 64 + c * 16);
        }
        asm volatile("cp.async.commit_group;\n" ::: "memory");

        if (tid < 96) qb[tid] = qkv_b[tid];
        if (tid < 64) {
            int p = 0;
            if (tid < WD) {
                int tr = tid / 7, tc = tid - tr * 7;
                int sh = wr * 7 + tr + 3; if (sh >= 56) sh -= 56;
                int sw = wc * 7 + tc + 3; if (sw >= 56) sw -= 56;
                p = sh * 56 + sw;
            }
            pixs[tid] = p;
        }
        for (int i = tid; i < 15 * XROW; i += 256)
            smw[OFF_X + 49 * XROW + i] = 0u;

        for (int i = tid; i < 1568; i += 256) {
            int t  = i >> 5;
            int c4 = (i & 31) << 2;
            int tr = t / 7, tc = t - tr * 7;
            int sh = wr * 7 + tr + 3; if (sh >= 56) sh -= 56;
            int sw = wc * 7 + tc + 3; if (sw >= 56) sw -= 56;
            float4 v = *(const float4*)&xb[(sh * 56 + sw) * EDIM + (half << 7) + c4];
            smw[OFF_X + t * XROW + (c4 >> 1)]     = packh2(v.x, v.y);
            smw[OFF_X + t * XROW + (c4 >> 1) + 1] = packh2(v.z, v.w);
        }
        asm volatile("cp.async.wait_group 0;\n" ::: "memory");
        __syncthreads();

        const int hl = warp >> 1;
        const int h  = (half << 2) + hl;
        const int wm = warp & 1;
        const int tb = wm << 5;
        const int r  = lane >> 2;
        const int cc = lane & 3;

        const uint32_t sbK = sb + ((OFF_KV + hl * 2560) << 2);
        const uint32_t sbV = sbK + (1280 << 2);
        const uint32_t sbW = sb + (OFF_W << 2);
        uint32_t* Ksm = smw + OFF_KV + hl * 2560;
        uint32_t* Vsm = Ksm + 1280;

        uint32_t xa[2][2][4];
        #pragma unroll
        for (int mt = 0; mt < 2; mt++)
            #pragma unroll
            for (int kt = 0; kt < 2; kt++) {
                uint32_t addr = sb +
                    (((tb + (mt << 4) + (lane & 15)) * XROW +
                      (hl << 4) + (kt << 3) + ((lane >> 4) << 2)) << 2);
                ldsm4(xa[mt][kt][0], xa[mt][kt][1], xa[mt][kt][2], xa[mt][kt][3], addr);
            }
        __syncthreads();   // X consumed; K/V may overwrite X region

        uint32_t qf[2][2][4];
        #pragma unroll
        for (int sec = 0; sec < 3; sec++) {
            uint32_t bf[2][2][4];
            #pragma unroll
            for (int g = 0; g < 2; g++)
                #pragma unroll
                for (int kt = 0; kt < 2; kt++) {
                    uint32_t addr = sbW +
                        (((sec * 32 + (g << 4) + (lane & 15)) * 20 +
                          (kt << 3) + ((lane >> 4) << 2)) << 2);
                    ldsm4(bf[g][kt][0], bf[g][kt][1], bf[g][kt][2], bf[g][kt][3], addr);
                }
            #pragma unroll
            for (int mt = 0; mt < 2; mt++) {
                int tok0 = tb + (mt << 4) + r;
                #pragma unroll
                for (int nt = 0; nt < 4; nt++) {
                    int n0 = nt << 3;
                    float b0 = qb[sec * 32 + n0 + (cc << 1)];
                    float b1 = qb[sec * 32 + n0 + (cc << 1) + 1];
                    float c[4] = {b0, b1, b0, b1};
                    int g = nt >> 1, hi = nt & 1;
                    #pragma unroll
                    for (int kt = 0; kt < 2; kt++) {
                        uint32_t bb[2];
                        bb[0] = hi ? bf[g][kt][1] : bf[g][kt][0];
                        bb[1] = hi ? bf[g][kt][3] : bf[g][kt][2];
                        mma_f16(c, xa[mt][kt], bb);
                    }
                    if (sec == 0) {
                        int kt2 = nt >> 1;
                        if ((nt & 1) == 0) {
                            qf[mt][kt2][0] = packh2(c[0] * SCALE, c[1] * SCALE);
                            qf[mt][kt2][1] = packh2(c[2] * SCALE, c[3] * SCALE);
                        } else {
                            qf[mt][kt2][2] = packh2(c[0] * SCALE, c[1] * SCALE);
                            qf[mt][kt2][3] = packh2(c[2] * SCALE, c[3] * SCALE);
                        }
                    } else if (sec == 1) {
                        Ksm[tok0 * 20 + (nt << 2) + cc]       = packh2(c[0], c[1]);
                        Ksm[(tok0 + 8) * 20 + (nt << 2) + cc] = packh2(c[2], c[3]);
                    } else {
                        Vsm[tok0 * 20 + (nt << 2) + cc]       = packh2(c[0], c[1]);
                        Vsm[(tok0 + 8) * 20 + (nt << 2) + cc] = packh2(c[2], c[3]);
                    }
                }
            }
        }

        asm volatile("bar.sync %0, 64;" :: "r"(hl + 8) : "memory");

        const __half2* tb2 = (const __half2*)g_bias;

        #pragma unroll
        for (int mt = 0; mt < 2; mt++) {
            int q0 = tb + (mt << 4) + r;
            int base0 = ((((cls << 3) + h) << 6) + q0) << 5;
            int base1 = base0 + (8 << 5);

            float sacc[8][4];
            #pragma unroll
            for (int nt = 0; nt < 8; nt++)
                #pragma unroll
                for (int i = 0; i < 4; i++) sacc[nt][i] = 0.f;

            #pragma unroll
            for (int g = 0; g < 4; g++)
                #pragma unroll
                for (int kt = 0; kt < 2; kt++) {
                    uint32_t r0, r1, r2, r3;
                    uint32_t addr = sbK +
                        ((((g << 4) + (lane & 15)) * 20 + (kt << 3) + ((lane >> 4) << 2)) << 2);
                    ldsm4(r0, r1, r2, r3, addr);
                    uint32_t blo[2] = {r0, r2};
                    uint32_t bhi[2] = {r1, r3};
                    mma_f16(sacc[(g << 1)],     qf[mt][kt], blo);
                    mma_f16(sacc[(g << 1) + 1], qf[mt][kt], bhi);
                }

            #pragma unroll
            for (int nt = 0; nt < 8; nt++) {
                float2 b0 = __half22float2(tb2[base0 + (nt << 2) + cc]);
                float2 b1 = __half22float2(tb2[base1 + (nt << 2) + cc]);
                sacc[nt][0] += b0.x; sacc[nt][1] += b0.y;
                sacc[nt][2] += b1.x; sacc[nt][3] += b1.y;
            }
            float m0 = -1e30f, m1 = -1e30f;
            #pragma unroll
            for (int nt = 0; nt < 8; nt++) {
                m0 = fmaxf(m0, fmaxf(sacc[nt][0], sacc[nt][1]));
                m1 = fmaxf(m1, fmaxf(sacc[nt][2], sacc[nt][3]));
            }
            m0 = fmaxf(m0, __shfl_xor_sync(0xffffffffu, m0, 1));
            m0 = fmaxf(m0, __shfl_xor_sync(0xffffffffu, m0, 2));
            m1 = fmaxf(m1, __shfl_xor_sync(0xffffffffu, m1, 1));
            m1 = fmaxf(m1, __shfl_xor_sync(0xffffffffu, m1, 2));
            float s0 = 0.f, s1 = 0.f;
            #pragma unroll
            for (int nt = 0; nt < 8; nt++) {
                sacc[nt][0] = __expf(sacc[nt][0] - m0); s0 += sacc[nt][0];
                sacc[nt][1] = __expf(sacc[nt][1] - m0); s0 += sacc[nt][1];
                sacc[nt][2] = __expf(sacc[nt][2] - m1); s1 += sacc[nt][2];
                sacc[nt][3] = __expf(sacc[nt][3] - m1); s1 += sacc[nt][3];
            }
            s0 += __shfl_xor_sync(0xffffffffu, s0, 1);
            s0 += __shfl_xor_sync(0xffffffffu, s0, 2);
            s1 += __shfl_xor_sync(0xffffffffu, s1, 1);
            s1 += __shfl_xor_sync(0xffffffffu, s1, 2);
            float inv0 = __frcp_rn(s0), inv1 = __frcp_rn(s1);

            uint32_t pf[4][4];
            #pragma unroll
            for (int nt = 0; nt < 8; nt++) {
                int kt2 = nt >> 1;
                uint32_t plo = packh2(sacc[nt][0] * inv0, sacc[nt][1] * inv0);
                uint32_t phi = packh2(sacc[nt][2] * inv1, sacc[nt][3] * inv1);
                if ((nt & 1) == 0) { pf[kt2][0] = plo; pf[kt2][1] = phi; }
                else               { pf[kt2][2] = plo; pf[kt2][3] = phi; }
            }

            float oacc[4][4];
            #pragma unroll
            for (int nt = 0; nt < 4; nt++)
                #pragma unroll
                for (int i = 0; i < 4; i++) oacc[nt][i] = 0.f;

            #pragma unroll
            for (int kt2 = 0; kt2 < 4; kt2++)
                #pragma unroll
                for (int vh2 = 0; vh2 < 2; vh2++) {
                    uint32_t r0, r1, r2, r3;
                    uint32_t addr = sbV +
                        ((((kt2 << 4) + (lane & 15)) * 20 + (vh2 << 3) + ((lane >> 4) << 2)) << 2);
                    ldsm4t(r0, r1, r2, r3, addr);
                    uint32_t blo[2] = {r0, r1};
                    uint32_t bhi[2] = {r2, r3};
                    mma_f16(oacc[(vh2 << 1)],     pf[kt2], blo);
                    mma_f16(oacc[(vh2 << 1) + 1], pf[kt2], bhi);
                }

            #pragma unroll
            for (int ntv = 0; ntv < 4; ntv++) {
                int col = (h << 5) + (ntv << 3) + (cc << 1);
                if (q0 < WD)
                    *(uint32_t*)&ob[pixs[q0] * EDIM + col] = packh2(oacc[ntv][0], oacc[ntv][1]);
                if (q0 + 8 < WD)
                    *(uint32_t*)&ob[pixs[q0 + 8] * EDIM + col] = packh2(oacc[ntv][2], oacc[ntv][3]);
            }
        }

        __syncthreads();
        if (tid == 0) {
            __threadfence();
            atomicAdd(&g_cnt[b], 1);
        }
    } else {
        // ================= proj path (R16, gated on counters) ==============
        const int pid = bi - ATT_BLOCKS;           // 0..3135
        const int rowBase = (pid >> 2) << 7;
        const int nBase   = (pid & 3) << 6;
        const int bf = rowBase / HWPIX;
        const int bl = (rowBase + 127) / HWPIX;

        if (tid == 0) {
            while (atomicAdd(&g_cnt[bf], 0) < 128) __nanosleep(128);
            if (bl != bf)
                while (atomicAdd(&g_cnt[bl], 0) < 128) __nanosleep(128);
        }
        __syncthreads();

        const int mW = (warp >> 1) << 5;
        const int nW = (warp & 1) << 5;
        const __half* A16 = g_mid;
        const __half* B16 = g_wpT;
        const uint32_t sbase = (uint32_t)__cvta_generic_to_shared(smw);

        float acc[2][4][4];
        #pragma unroll
        for (int mt = 0; mt < 2; mt++)
            #pragma unroll
            for (int nt = 0; nt < 4; nt++)
                #pragma unroll
                for (int i = 0; i < 4; i++)
                    acc[mt][nt][i] = 0.f;

        #pragma unroll
        for (int l = 0; l < 8; l++) {
            int idx = tid + (l << 8);
            int row = idx >> 5, c16 = idx & 31;
            cpasync16(sbase + ((PJ_BOFF + row * 132 + (c16 << 2)) << 2),
                      &B16[(size_t)(nBase + row) * 256 + (c16 << 3)]);
        }
        #pragma unroll
        for (int l = 0; l < 2; l++) {
            int idx = tid + (l << 8);
            int row = idx >> 2, c = idx & 3;
            cpasync16(sbase + ((PJ_AOFF + row * 20 + (c << 2)) << 2),
                      &A16[(size_t)(rowBase + row) * 256 + (c << 3)]);
        }
        asm volatile("cp.async.commit_group;\n" ::: "memory");
        #pragma unroll
        for (int l = 0; l < 2; l++) {
            int idx = tid + (l << 8);
            int row = idx >> 2, c = idx & 3;
            cpasync16(sbase + ((PJ_AOFF + 2560 + row * 20 + (c << 2)) << 2),
                      &A16[(size_t)(rowBase + row) * 256 + 32 + (c << 3)]);
        }
        asm volatile("cp.async.commit_group;\n" ::: "memory");

        for (int kc = 0; kc < 8; kc++) {
            int buf = kc & 1;
            if (kc < 7) asm volatile("cp.async.wait_group 1;\n" ::: "memory");
            else        asm volatile("cp.async.wait_group 0;\n" ::: "memory");
            __syncthreads();

            const uint32_t sbA = sbase + ((PJ_AOFF + buf * 2560) << 2);
            const uint32_t sbB = sbase + (PJ_BOFF << 2);
            #pragma unroll
            for (int kt = 0; kt < 2; kt++) {
                int bko = (kc << 4) + (kt << 3);
                uint32_t a[2][4];
                #pragma unroll
                for (int mt2 = 0; mt2 < 2; mt2++) {
                    uint32_t addr = sbA +
                        (((mW + (mt2 << 4) + (lane & 15)) * 20 +
                          (kt << 3) + ((lane >> 4) << 2)) << 2);
                    ldsm4(a[mt2][0], a[mt2][1], a[mt2][2], a[mt2][3], addr);
                }
                uint32_t bb[4][2];
                #pragma unroll
                for (int g = 0; g < 2; g++) {
                    uint32_t r0, r1, r2, r3;
                    uint32_t addr = sbB +
                        (((nW + (g << 4) + (lane & 15)) * 132 +
                          bko + ((lane >> 4) << 2)) << 2);
                    ldsm4(r0, r1, r2, r3, addr);
                    bb[(g << 1)][0]     = r0; bb[(g << 1)][1]     = r2;
                    bb[(g << 1) + 1][0] = r1; bb[(g << 1) + 1][1] = r3;
                }
                #pragma unroll
                for (int mt2 = 0; mt2 < 2; mt2++)
                    #pragma unroll
                    for (int nt = 0; nt < 4; nt++)
                        mma_f16(acc[mt2][nt], a[mt2], bb[nt]);
            }
            __syncthreads();

            if (kc < 6) {
                int k0 = (kc + 2) << 5;
                #pragma unroll
                for (int l = 0; l < 2; l++) {
                    int idx = tid + (l << 8);
                    int row = idx >> 2, c = idx & 3;
                    cpasync16(sbase + ((PJ_AOFF + buf * 2560 + row * 20 + (c << 2)) << 2),
                              &A16[(size_t)(rowBase + row) * 256 + k0 + (c << 3)]);
                }
                asm volatile("cp.async.commit_group;\n" ::: "memory");
            }
        }

        #pragma unroll
        for (int mt2 = 0; mt2 < 2; mt2++) {
            int row = rowBase + mW + (mt2 << 4) + (lane >> 2);
            #pragma unroll
            for (int nt = 0; nt < 4; nt++) {
                int col = nBase + nW + (nt << 3) + ((lane & 3) << 1);
                float b0 = pb[col], b1 = pb[col + 1];
                float2 v0 = make_float2(acc[mt2][nt][0] + b0, acc[mt2][nt][1] + b1);
                float2 v1 = make_float2(acc[mt2][nt][2] + b0, acc[mt2][nt][3] + b1);
                *(float2*)&out[(size_t)row * 256 + col]       = v0;
                *(float2*)&out[(size_t)(row + 8) * 256 + col] = v1;
            }
        }
    }
}

extern "C" void kernel_launch(void* const* d_in, const int* in_sizes, int n_in,
                              void* d_out, int out_size)
{
    (void)in_sizes; (void)n_in; (void)out_size;
    const float* x      = (const float*)d_in[0];
    const float* qkv_w  = (const float*)d_in[1];
    const float* qkv_b  = (const float*)d_in[2];
    const float* proj_w = (const float*)d_in[3];
    const float* proj_b = (const float*)d_in[4];
    const float* rpb    = (const float*)d_in[5];
    float* out = (float*)d_out;

    cudaFuncSetAttribute(swin_fused_kernel,
                         cudaFuncAttributeMaxDynamicSharedMemorySize, FU_SMEM_BYTES);

    swin_prep_kernel<<<512, 256>>>(qkv_w, proj_w, rpb);
    swin_fused_kernel<<<ATT_BLOCKS + 3136, 256, FU_SMEM_BYTES>>>(x, qkv_b, proj_b, out);
}